// round 9
// baseline (speedup 1.0000x reference)
#include <cuda_runtime.h>
#include <cuda_fp16.h>
#include <math.h>
#include <stdint.h>

#define NTOK 4096
#define CDIM 1024
#define HDIM 4096
#define NEXP 8
#define NSLOT (NTOK * 2)
#define KS 4                         // gemm2 k-splits (1024 K each)
#define CVT2_JOBS 128

// GEMM geometry: block tile 256(M) x 128(N) x 64(K) fp16, 512 threads = 16 warps (4m x 4n)
#define STAGE_BYTES 49152            // A 32KB + B 16KB
#define SMEM_BYTES  (3 * STAGE_BYTES)

// ---------------- static device scratch ----------------
__device__ int g_counts[NEXP];
__device__ int g_offsets[NEXP + 1];
__device__ int g_cursor[NEXP];
__device__ __align__(16) int g_rtok[NSLOT];
__device__ int g_e1[NTOK], g_e2[NTOK];
__device__ int g_s1[NTOK], g_s2[NTOK];
__device__ float g_w1[NTOK], g_w2[NTOK];
__device__ __align__(256) __half g_x16[(size_t)NTOK * CDIM];          // 8 MiB
__device__ __align__(256) __half g_w1h[(size_t)NEXP * CDIM * HDIM];   // 64 MiB
__device__ __align__(256) __half g_w2h[(size_t)NEXP * HDIM * CDIM];   // 64 MiB
__device__ __align__(256) __half g_h[(size_t)NSLOT * HDIM];           // 64 MiB
__device__ __align__(256) __half g_yp[(size_t)KS * NSLOT * CDIM];     // 64 MiB fp16 partials

// job bookkeeping (reset each launch by k_prefix)
__device__ int g_jobctr;
__device__ int g_done1[NEXP];
__device__ int g_cvt2done;
__device__ int g_j1end[NEXP], g_j2end[NEXP];
__device__ int g_need[NEXP];
__device__ int g_T1, g_T2;

// ---------------- helpers ----------------
__device__ __forceinline__ uint32_t smem_u32(const void* p) {
    uint32_t a;
    asm("{ .reg .u64 t; cvta.to.shared.u64 t, %1; cvt.u32.u64 %0, t; }" : "=r"(a) : "l"(p));
    return a;
}
#define SWZ(o)    ((o) ^ ((((uint32_t)(o)) >> 3) & 0x70u))   // 128B rows
#define SWZ256(o) ((o) ^ ((((uint32_t)(o)) >> 4) & 0x70u))   // 256B rows

__device__ __forceinline__ void cp16(uint32_t dst, const void* src) {
    asm volatile("cp.async.cg.shared.global [%0], [%1], 16;" :: "r"(dst), "l"(src) : "memory");
}
__device__ __forceinline__ void ldsm4(uint32_t& r0, uint32_t& r1, uint32_t& r2, uint32_t& r3, uint32_t a) {
    asm volatile("ldmatrix.sync.aligned.m8n8.x4.shared.b16 {%0,%1,%2,%3}, [%4];"
                 : "=r"(r0), "=r"(r1), "=r"(r2), "=r"(r3) : "r"(a));
}
__device__ __forceinline__ void ldsm4t(uint32_t& r0, uint32_t& r1, uint32_t& r2, uint32_t& r3, uint32_t a) {
    asm volatile("ldmatrix.sync.aligned.m8n8.x4.trans.shared.b16 {%0,%1,%2,%3}, [%4];"
                 : "=r"(r0), "=r"(r1), "=r"(r2), "=r"(r3) : "r"(a));
}
__device__ __forceinline__ void mma_f16(float* c, uint32_t a0, uint32_t a1, uint32_t a2, uint32_t a3,
                                        uint32_t b0, uint32_t b1) {
    asm volatile(
        "mma.sync.aligned.m16n8k16.row.col.f32.f16.f16.f32 "
        "{%0,%1,%2,%3}, {%4,%5,%6,%7}, {%8,%9}, {%0,%1,%2,%3};"
        : "+f"(c[0]), "+f"(c[1]), "+f"(c[2]), "+f"(c[3])
        : "r"(a0), "r"(a1), "r"(a2), "r"(a3), "r"(b0), "r"(b1));
}
__device__ __forceinline__ float gelu_exact(float v) {
    return 0.5f * v * (1.0f + erff(v * 0.70710678118654752f));
}

// ---------------- fp32->fp16 convert: x + W1 (W2 converted inside persistent kernel) ----------------
#define NX4 (NTOK * CDIM / 4)
#define NW4 (NEXP * CDIM * HDIM / 4)
__global__ void k_cvt(const float4* __restrict__ x, const float4* __restrict__ W1) {
    uint32_t i = blockIdx.x * blockDim.x + threadIdx.x;
    if (i < NEXP) g_counts[i] = 0;
    const float4* src;
    uint2* dst;
    uint32_t idx;
    if (i < NX4) {
        src = x;  dst = (uint2*)g_x16; idx = i;
    } else if (i < NX4 + NW4) {
        src = W1; dst = (uint2*)g_w1h; idx = i - NX4;
    } else return;
    float4 v = src[idx];
    __half2 lo = __floats2half2_rn(v.x, v.y);
    __half2 hi = __floats2half2_rn(v.z, v.w);
    uint2 o;
    o.x = *(uint32_t*)&lo;
    o.y = *(uint32_t*)&hi;
    dst[idx] = o;
}

// ---------------- routing kernels ----------------
__global__ void k_gate(const float* __restrict__ x, const float* __restrict__ Wg,
                       const float* __restrict__ bg) {
    int warp = (blockIdx.x * blockDim.x + threadIdx.x) >> 5;
    int lane = threadIdx.x & 31;
    if (warp >= NTOK) return;
    const float* xr = x + (size_t)warp * CDIM;
    float acc[NEXP];
#pragma unroll
    for (int e = 0; e < NEXP; e++) acc[e] = 0.f;
    for (int k = lane; k < CDIM; k += 32) {
        float xv = xr[k];
        const float* wr = Wg + k * NEXP;
#pragma unroll
        for (int e = 0; e < NEXP; e++) acc[e] = fmaf(xv, wr[e], acc[e]);
    }
#pragma unroll
    for (int off = 16; off; off >>= 1)
#pragma unroll
        for (int e = 0; e < NEXP; e++)
            acc[e] += __shfl_xor_sync(0xffffffffu, acc[e], off);
    if (lane == 0) {
#pragma unroll
        for (int e = 0; e < NEXP; e++) acc[e] += bg[e];
        int b1i = 0; float b1v = acc[0];
#pragma unroll
        for (int e = 1; e < NEXP; e++) if (acc[e] > b1v) { b1v = acc[e]; b1i = e; }
        int b2i = -1; float b2v = -3.0e38f;
#pragma unroll
        for (int e = 0; e < NEXP; e++)
            if (e != b1i && acc[e] > b2v) { b2v = acc[e]; b2i = e; }
        float p2 = expf(b2v - b1v);
        float inv = 1.f / (1.f + p2);
        g_e1[warp] = b1i; g_e2[warp] = b2i;
        g_w1[warp] = inv; g_w2[warp] = p2 * inv;
        atomicAdd(&g_counts[b1i], 1);
        atomicAdd(&g_counts[b2i], 1);
    }
}

__global__ void k_prefix() {
    if (threadIdx.x == 0 && blockIdx.x == 0) {
        int off = 0, t1 = 0, t2 = 0;
        for (int e = 0; e < NEXP; e++) {
            g_offsets[e] = off;
            g_cursor[e]  = off;
            int ne = g_counts[e];
            off += ne;
            int mt = (ne + 255) >> 8;
            t1 += mt * 32;
            t2 += mt * 8 * KS;
            g_j1end[e] = t1;
            g_j2end[e] = t2;
            g_need[e]  = mt * 32;
            g_done1[e] = 0;
        }
        g_offsets[NEXP] = off;
        g_T1 = t1; g_T2 = t2;
        g_jobctr = 0;
        g_cvt2done = 0;
    }
}

__global__ void k_scatter() {
    int t = blockIdx.x * blockDim.x + threadIdx.x;
    if (t >= NTOK) return;
    int s1 = atomicAdd(&g_cursor[g_e1[t]], 1);
    g_rtok[s1] = t; g_s1[t] = s1;
    int s2 = atomicAdd(&g_cursor[g_e2[t]], 1);
    g_rtok[s2] = t; g_s2[t] = s2;
}

// ---------------- fp16 HMMA mainloop (256x128x64, 512 thr, 3-stage cp.async) ----------------
template <int NCH>
__device__ __forceinline__ void mma_loop(
    uint32_t sb, const __half* const (&ap)[4], const __half* bsrc, int ldb,
    int tid, float (&acc)[4][4][4])
{
    const int lane = tid & 31, wid = tid >> 5;
    const int wm = (wid >> 2) * 64, wn = (wid & 3) * 32;

    uint32_t adst[4];
#pragma unroll
    for (int j = 0; j < 4; j++)
        adst[j] = SWZ((uint32_t)((tid >> 3) + 64 * j) * 128u + (uint32_t)(tid & 7) * 16u);
    uint32_t bdst[2];
#pragma unroll
    for (int j = 0; j < 2; j++)
        bdst[j] = 32768u + SWZ256((uint32_t)((tid >> 4) + 32 * j) * 256u + (uint32_t)(tid & 15) * 16u);

#define CPS(ch, s)                                                                    \
    {                                                                                 \
        uint32_t base = sb + (uint32_t)(s) * STAGE_BYTES;                             \
_Pragma("unroll")                                                                     \
        for (int j = 0; j < 4; j++)                                                   \
            cp16(base + adst[j], ap[j] + (size_t)(ch) * 64);                          \
_Pragma("unroll")                                                                     \
        for (int j = 0; j < 2; j++)                                                   \
            cp16(base + bdst[j], bsrc + ((size_t)(ch) * 64 + 32 * j) * ldb);          \
    }

    CPS(0, 0);
    asm volatile("cp.async.commit_group;" ::: "memory");
    CPS(1, 1);
    asm volatile("cp.async.commit_group;" ::: "memory");

    for (int i = 0; i < NCH; i++) {
        const bool pf = (i + 2) < NCH;
        asm volatile("cp.async.wait_group 1;" ::: "memory");
        __syncthreads();
        if (pf) CPS(i + 2, (i + 2) % 3);
        asm volatile("cp.async.commit_group;" ::: "memory");

        uint32_t As = sb + (uint32_t)(i % 3) * STAGE_BYTES;
        uint32_t Bb = As + 32768u;
#pragma unroll
        for (int ks = 0; ks < 4; ks++) {
            uint32_t bq[4][2];
#pragma unroll
            for (int p = 0; p < 2; p++) {
                int g = lane >> 3, r = lane & 7;
                uint32_t krow = (uint32_t)(ks * 16 + (g & 1) * 8 + r);
                uint32_t nby  = (uint32_t)(wn + p * 16 + (g >> 1) * 8) * 2u;
                uint32_t addr = Bb + SWZ256(krow * 256u + nby);
                ldsm4t(bq[2 * p][0], bq[2 * p][1], bq[2 * p + 1][0], bq[2 * p + 1][1], addr);
            }
#pragma unroll
            for (int ms = 0; ms < 4; ms++) {
                uint32_t row  = (uint32_t)(wm + ms * 16 + (lane & 15));
                uint32_t colb = (uint32_t)(ks * 32 + (lane >> 4) * 16);
                uint32_t addr = As + SWZ(row * 128u + colb);
                uint32_t a0, a1, a2, a3;
                ldsm4(a0, a1, a2, a3, addr);
#pragma unroll
                for (int ns = 0; ns < 4; ns++)
                    mma_f16(acc[ms][ns], a0, a1, a2, a3, bq[ns][0], bq[ns][1]);
            }
        }
    }
#undef CPS
}

// ---------------- persistent fused GEMM kernel ----------------
__global__ __launch_bounds__(512, 1)
void k_persist(const float* __restrict__ W2, const float* __restrict__ b1,
               const float* __restrict__ b2) {
    extern __shared__ __align__(1024) char smem[];
    __shared__ int s_job;
    const uint32_t sb = smem_u32(smem);
    const int tid = threadIdx.x;
    const int T1 = g_T1, T2 = g_T2;

    const int lane = tid & 31, wid = tid >> 5;
    const int grp = lane >> 2, tq = lane & 3;
    const int wm = (wid >> 2) * 64, wn = (wid & 3) * 32;

    for (;;) {
        __syncthreads();                       // stages/s_job from prior job fully consumed
        if (tid == 0) s_job = atomicAdd(&g_jobctr, 1);
        __syncthreads();
        const int j = s_job;
        if (j >= T1 + CVT2_JOBS + T2) break;

        if (j < T1) {
            // ---------------- GEMM1 tile job ----------------
            int e = 0;
#pragma unroll
            for (int q = 0; q < NEXP - 1; q++) if (j >= g_j1end[q] && e == q) e = q + 1;
            const int lstart = (e == 0) ? 0 : g_j1end[e - 1];
            const int local = j - lstart;
            const int m0 = (local >> 5) * 256;
            const int n0 = (local & 31) * 128;
            const int off = g_offsets[e];
            const int ne  = g_offsets[e + 1] - off;

            const __half* ap[4];
#pragma unroll
            for (int q = 0; q < 4; q++) {
                int r = m0 + (tid >> 3) + 64 * q;
                int tok = g_rtok[off + (r < ne ? r : 0)];
                ap[q] = g_x16 + (size_t)tok * CDIM + (tid & 7) * 8;
            }
            const __half* bsrc = g_w1h + (size_t)e * CDIM * HDIM +
                                 (size_t)(tid >> 4) * HDIM + n0 + (tid & 15) * 8;

            float acc[4][4][4];
#pragma unroll
            for (int a = 0; a < 4; a++)
#pragma unroll
                for (int b = 0; b < 4; b++)
#pragma unroll
                    for (int c = 0; c < 4; c++) acc[a][b][c] = 0.f;

            mma_loop<CDIM / 64>(sb, ap, bsrc, HDIM, tid, acc);

            const float* brow = b1 + (size_t)e * HDIM + n0 + wn;
#pragma unroll
            for (int ms = 0; ms < 4; ms++)
#pragma unroll
                for (int h = 0; h < 2; h++) {
                    int r = m0 + wm + ms * 16 + grp + h * 8;
                    if (r < ne) {
                        __half* hrow = g_h + (size_t)(off + r) * HDIM + n0 + wn;
#pragma unroll
                        for (int ns = 0; ns < 4; ns++) {
                            int col = ns * 8 + 2 * tq;
                            __half2 o = __floats2half2_rn(
                                gelu_exact(acc[ms][ns][h * 2 + 0] + brow[col]),
                                gelu_exact(acc[ms][ns][h * 2 + 1] + brow[col + 1]));
                            *(__half2*)(hrow + col) = o;
                        }
                    }
                }
            __threadfence();
            __syncthreads();
            if (tid == 0) atomicAdd(&g_done1[e], 1);

        } else if (j < T1 + CVT2_JOBS) {
            // ---------------- W2 fp32->fp16 convert job ----------------
            const int idx = j - T1;
            const int per = NW4 / CVT2_JOBS;               // float4s per job
            const float4* src = (const float4*)W2 + (size_t)idx * per;
            uint2* dst = (uint2*)g_w2h + (size_t)idx * per;
            for (int i = tid; i < per; i += 512) {
                float4 v = src[i];
                __half2 lo = __floats2half2_rn(v.x, v.y);
                __half2 hi = __floats2half2_rn(v.z, v.w);
                uint2 o;
                o.x = *(uint32_t*)&lo;
                o.y = *(uint32_t*)&hi;
                dst[i] = o;
            }
            __threadfence();
            __syncthreads();
            if (tid == 0) atomicAdd(&g_cvt2done, 1);

        } else {
            // ---------------- GEMM2 split-K tile job ----------------
            const int j2 = j - T1 - CVT2_JOBS;
            int e = 0;
#pragma unroll
            for (int q = 0; q < NEXP - 1; q++) if (j2 >= g_j2end[q] && e == q) e = q + 1;
            const int lstart = (e == 0) ? 0 : g_j2end[e - 1];
            const int local = j2 - lstart;
            const int m0 = (local / (8 * KS)) * 256;
            const int rem = local % (8 * KS);
            const int n0 = (rem / KS) * 128;
            const int kp = rem % KS;                         // k-split index
            const int off = g_offsets[e];
            const int ne  = g_offsets[e + 1] - off;

            if (tid == 0) {
                const int need = g_need[e];
                while (atomicAdd(&g_done1[e], 0) < need || atomicAdd(&g_cvt2done, 0) < CVT2_JOBS)
                    __nanosleep(200);
            }
            __syncthreads();
            __threadfence();                                  // acquire for g_h / g_w2h

            const __half* ap[4];
#pragma unroll
            for (int q = 0; q < 4; q++) {
                int r = m0 + (tid >> 3) + 64 * q;
                if (r >= ne) r = ne - 1;
                ap[q] = g_h + (size_t)(off + r) * HDIM + kp * 1024 + (tid & 7) * 8;
            }
            const __half* bsrc = g_w2h + (size_t)e * HDIM * CDIM +
                                 (size_t)(kp * 1024 + (tid >> 4)) * CDIM + n0 + (tid & 15) * 8;

            float acc[4][4][4];
#pragma unroll
            for (int a = 0; a < 4; a++)
#pragma unroll
                for (int b = 0; b < 4; b++)
#pragma unroll
                    for (int c = 0; c < 4; c++) acc[a][b][c] = 0.f;

            mma_loop<1024 / 64>(sb, ap, bsrc, CDIM, tid, acc);

            __half* yplane = g_yp + (size_t)kp * NSLOT * CDIM;
#pragma unroll
            for (int ms = 0; ms < 4; ms++)
#pragma unroll
                for (int h = 0; h < 2; h++) {
                    int r = m0 + wm + ms * 16 + grp + h * 8;
                    if (r < ne) {
                        __half* yrow = yplane + (size_t)(off + r) * CDIM + n0 + wn;
#pragma unroll
                        for (int ns = 0; ns < 4; ns++) {
                            int col = ns * 8 + 2 * tq;
                            __half2 o = __floats2half2_rn(acc[ms][ns][h * 2 + 0],
                                                          acc[ms][ns][h * 2 + 1]);
                            *(__half2*)(yrow + col) = o;
                        }
                    }
                }
        }
    }
}

// ---------------- combine: out[t] = w1*(sum_p yp[s1]+b2[e1]) + w2*(sum_p yp[s2]+b2[e2]) ----------------
__global__ void k_combine(const float* __restrict__ b2, float* __restrict__ out) {
    int t = blockIdx.x;
    int c = threadIdx.x * 4;
    float w1 = g_w1[t], w2 = g_w2[t];
    int s1 = g_s1[t], s2 = g_s2[t];
    int e1 = g_e1[t], e2 = g_e2[t];
    float a0 = 0.f, a1 = 0.f, a2 = 0.f, a3 = 0.f;
    float d0 = 0.f, d1 = 0.f, d2 = 0.f, d3 = 0.f;
#pragma unroll
    for (int p = 0; p < KS; p++) {
        const __half2* r1 = (const __half2*)(g_yp + ((size_t)p * NSLOT + s1) * CDIM + c);
        const __half2* r2 = (const __half2*)(g_yp + ((size_t)p * NSLOT + s2) * CDIM + c);
        float2 u0 = __half22float2(r1[0]);
        float2 u1 = __half22float2(r1[1]);
        float2 v0 = __half22float2(r2[0]);
        float2 v1 = __half22float2(r2[1]);
        a0 += u0.x; a1 += u0.y; a2 += u1.x; a3 += u1.y;
        d0 += v0.x; d1 += v0.y; d2 += v1.x; d3 += v1.y;
    }
    const float4 bb1 = *(const float4*)(b2 + (size_t)e1 * CDIM + c);
    const float4 bb2 = *(const float4*)(b2 + (size_t)e2 * CDIM + c);
    float4 o;
    o.x = w1 * (a0 + bb1.x) + w2 * (d0 + bb2.x);
    o.y = w1 * (a1 + bb1.y) + w2 * (d1 + bb2.y);
    o.z = w1 * (a2 + bb1.z) + w2 * (d2 + bb2.z);
    o.w = w1 * (a3 + bb1.w) + w2 * (d3 + bb2.w);
    *(float4*)(out + (size_t)t * CDIM + c) = o;
}

extern "C" void kernel_launch(void* const* d_in, const int* in_sizes, int n_in,
                              void* d_out, int out_size) {
    const float* x  = (const float*)d_in[0];
    const float* Wg = (const float*)d_in[1];
    const float* bg = (const float*)d_in[2];
    const float* W1 = (const float*)d_in[3];
    const float* b1 = (const float*)d_in[4];
    const float* W2 = (const float*)d_in[5];
    const float* b2 = (const float*)d_in[6];
    float* out = (float*)d_out;

    cudaFuncSetAttribute(k_persist, cudaFuncAttributeMaxDynamicSharedMemorySize, SMEM_BYTES);

    const int ncvt = NX4 + NW4;
    k_cvt<<<(ncvt + 255) / 256, 256>>>((const float4*)x, (const float4*)W1);

    k_gate<<<(NTOK * 32 + 255) / 256, 256>>>(x, Wg, bg);
    k_prefix<<<1, 1>>>();
    k_scatter<<<(NTOK + 255) / 256, 256>>>();

    k_persist<<<148, 512, SMEM_BYTES>>>(W2, b1, b2);
    k_combine<<<NTOK, 256>>>(b2, out);
}